// round 13
// baseline (speedup 1.0000x reference)
#include <cuda_runtime.h>
#include <cuda_fp16.h>
#include <cstdint>

#define Bv 16
#define Cv 64
#define Hv 128
#define Wv 128
#define HCv 64
#define NROWS 2048
#define GRID 148

// Pre-baked W image (fp16): [chunk(3)][m(256)][k(64) octet-swizzled] = 96 KB
__device__ __align__(16) uint16_t g_wimg[3 * 256 * 64];
// Pre-rounded X plane (fp16), layout [b][ic][h][w]
#define XN ((size_t)Bv * Cv * Hv * Wv)
__device__ __align__(16) __half g_xhi[XN];

// ---- smem map (bytes) ----
// W resident: 3 x 32KB at 0 ; XBUF: 2 x 16KB at 98304
// GATES fp16 at 131072: [m(256)][138 halves] (stride 276B = 69 words == 5 mod 32)
// PS (scan partials, fp32 pairs) at 201728 (4KB)
#define XBUF_B 98304
#define GATE_B 131072
#define GROW_B 276
#define PS_B   201728
#define SMEM_BYTES 205824

extern __shared__ uint32_t smw[];

__device__ __forceinline__ uint32_t smem_u32(const void* p) {
    uint32_t a;
    asm("{ .reg .u64 t; cvta.to.shared.u64 t, %1; cvt.u32.u64 %0, t; }"
        : "=r"(a) : "l"(p));
    return a;
}

__device__ __forceinline__ float tanh_f(float x) {
    float y;
    asm("tanh.approx.f32 %0, %1;" : "=f"(y) : "f"(x));
    return y;
}
__device__ __forceinline__ float sigmoid_f(float x) {
    return fmaf(tanh_f(0.5f * x), 0.5f, 0.5f);
}

__device__ __forceinline__ void mma_f16(float* c, const uint32_t* a,
                                        uint32_t b0, uint32_t b1) {
    asm volatile(
        "mma.sync.aligned.m16n8k16.row.col.f32.f16.f16.f32 "
        "{%0,%1,%2,%3}, {%4,%5,%6,%7}, {%8,%9}, {%0,%1,%2,%3};\n"
        : "+f"(c[0]), "+f"(c[1]), "+f"(c[2]), "+f"(c[3])
        : "r"(a[0]), "r"(a[1]), "r"(a[2]), "r"(a[3]), "r"(b0), "r"(b1));
}

#define LDM4(R, addr) \
    asm volatile("ldmatrix.sync.aligned.m8n8.x4.shared.b16 {%0,%1,%2,%3}, [%4];" \
        : "=r"((R)[0]), "=r"((R)[1]), "=r"((R)[2]), "=r"((R)[3]) : "r"(addr))
#define LDM4T(R, addr) \
    asm volatile("ldmatrix.sync.aligned.m8n8.x4.trans.shared.b16 {%0,%1,%2,%3}, [%4];" \
        : "=r"((R)[0]), "=r"((R)[1]), "=r"((R)[2]), "=r"((R)[3]) : "r"(addr))
#define CPA16(dst, src) \
    asm volatile("cp.async.ca.shared.global [%0], [%1], 16;" :: "r"(dst), "l"(src))
#define CPA16Z(dst, src, sz) \
    asm volatile("cp.async.ca.shared.global [%0], [%1], 16, %2;" \
                 :: "r"(dst), "l"(src), "r"(sz))
#define CPA_COMMIT() asm volatile("cp.async.commit_group;" ::: "memory")
#define CPA_WAIT0()  asm volatile("cp.async.wait_group 0;" ::: "memory")

__device__ __forceinline__ void sts32(uint32_t a, uint32_t v) {
    asm volatile("st.shared.u32 [%0], %1;" :: "r"(a), "r"(v) : "memory");
}
__device__ __forceinline__ uint32_t lds32(uint32_t a) {
    uint32_t v;
    asm volatile("ld.shared.u32 %0, [%1];" : "=r"(v) : "r"(a));
    return v;
}
__device__ __forceinline__ float2 h2f2(uint32_t w) {
    return __half22float2(*reinterpret_cast<__half2*>(&w));
}

// ---------------------------------------------------------------- prep kernel
__global__ void __launch_bounds__(256)
prep_xw(const float* __restrict__ x, const float* __restrict__ wgt) {
    if (blockIdx.x < 192) {
        int k = blockIdx.x;
        int m = threadIdx.x;
        float v = wgt[m * 192 + k];
        int c = k >> 6, kl = k & 63, o = kl >> 3, e = kl & 7;
        g_wimg[c * 16384 + m * 64 + (((o ^ (m & 7)) << 3) + e)] =
            __half_as_ushort(__float2half_rn(v));
    }
    size_t i = ((size_t)blockIdx.x * 256 + threadIdx.x) * 8;
    float4 a = *reinterpret_cast<const float4*>(x + i);
    float4 c = *reinterpret_cast<const float4*>(x + i + 4);
    float vf[8] = {a.x, a.y, a.z, a.w, c.x, c.y, c.z, c.w};
    uint32_t hw[4];
#pragma unroll
    for (int j = 0; j < 4; j++) {
        __half2 hh = __float22half2_rn(make_float2(vf[2 * j], vf[2 * j + 1]));
        hw[j] = *reinterpret_cast<uint32_t*>(&hh);
    }
    *reinterpret_cast<uint4*>(g_xhi + i) = make_uint4(hw[0], hw[1], hw[2], hw[3]);
}

// ---------------------------------------------------------------- persistent fused kernel
// 148 CTAs (1/SM), 256 threads = 8 warps (4m x 2n), warp tile 64m x 64w.
// W (96KB) staged once; X streamed per chunk; fp16 gates; register partials.
__global__ void __launch_bounds__(256, 1)
rowlstm_fused(const float* __restrict__ bias, float* __restrict__ out) {
    const int tid = threadIdx.x;
    const int lane = tid & 31;
    const int wid = tid >> 5;
    const int mw = wid & 3;          // gate index q
    const int nw = wid >> 2;         // 0..1 (64 w each)
    const int r = lane >> 2, cl = lane & 3;

    const uint32_t smb = smem_u32(smw);

    const int l7 = lane & 7, l15 = lane & 15, lk = lane >> 4;
    const int krl = l7 + ((lane & 16) >> 1);
    const int wo = (lane >> 3) & 1;

    uint64_t gw, gxh;
    asm("cvta.to.global.u64 %0, %1;" : "=l"(gw) : "l"((const void*)g_wimg));
    asm("cvta.to.global.u64 %0, %1;" : "=l"(gxh) : "l"((const void*)g_xhi));

    float blo[4], bhi[4];
#pragma unroll
    for (int mt = 0; mt < 4; mt++) {
        blo[mt] = bias[mw * 64 + mt * 16 + r];
        bhi[mt] = bias[mw * 64 + mt * 16 + 8 + r];
    }
    const bool isg = (mw == 3);

    // scan mapping: 8 seg (16 w each) x 32 threads; each thread: hc=hcl, hcl+32
    const int seg = tid >> 5;
    const int hcl = tid & 31;
    const uint32_t gsc0 = smb + GATE_B + (uint32_t)hcl * GROW_B + (uint32_t)seg * 32;
    const uint32_t gsc1 = gsc0 + 32u * GROW_B;

#define STAGE_X(bb_, hh_, cn, db)                                           \
    do {                                                                    \
        _Pragma("unroll") for (int t = 0; t < 4; t++) {                     \
            int g = t * 256 + tid;                                          \
            int krow = g >> 4;                                              \
            int woct = g & 15;                                              \
            int kg = (cn) * 64 + krow;                                      \
            int ic = kg / 3;                                                \
            int kh = kg - 3 * ic;                                           \
            int hp = (hh_) + kh - 2;                                        \
            int sz = (hp >= 0) ? 16 : 0;                                    \
            int hpc = (hp >= 0) ? hp : 0;                                   \
            size_t eoff = (((size_t)((bb_) * Cv + ic) * Hv + hpc) * Wv +    \
                           woct * 8) * 2;                                   \
            uint32_t dst = smb + XBUF_B + (db) * 16384 + krow * 256 +       \
                           ((woct ^ (krow & 7)) << 4);                      \
            CPA16Z(dst, gxh + eoff, sz);                                    \
        }                                                                   \
    } while (0)

    // ---- preamble: W (96KB, once per SM) + first row chunk0
    {
#pragma unroll
        for (int j = 0; j < 24; j++)
            CPA16(smb + tid * 16 + j * 4096, gw + tid * 16 + j * 4096);
        STAGE_X(blockIdx.x >> 7, blockIdx.x & 127, 0, 0);
        CPA_COMMIT();
        CPA_WAIT0();
        __syncthreads();
    }

    int p = 0;
#pragma unroll 1
    for (int bh = blockIdx.x; bh < NROWS; bh += GRID) {
        const int b = bh >> 7, h = bh & 127;

        float acc[4][8][4];
#pragma unroll
        for (int mt = 0; mt < 4; mt++)
#pragma unroll
            for (int nt = 0; nt < 8; nt++)
#pragma unroll
                for (int q = 0; q < 4; q++) acc[mt][nt][q] = 0.0f;

#pragma unroll
        for (int c = 0; c < 3; c++) {
            const int db = (p + c) & 1;
            if (c < 2) {
                STAGE_X(b, h, c + 1, db ^ 1);
                CPA_COMMIT();
            }

            const uint32_t a_h = smb + c * 32768 + (mw * 64 + l15) * 128;
            uint32_t bb[4];
#pragma unroll
            for (int np = 0; np < 4; np++) {
                int oct = nw * 8 + np * 2 + wo;
                bb[np] = smb + XBUF_B + db * 16384 + krl * 256 + ((oct ^ l7) << 4);
            }
#pragma unroll
            for (int ks = 0; ks < 4; ks++) {
                uint32_t Bh[4][4];
#pragma unroll
                for (int np = 0; np < 4; np++)
                    LDM4T(Bh[np], bb[np] + ks * 4096);
                const uint32_t swA = (uint32_t)(((2 * ks + lk) ^ l7) << 4);
#pragma unroll
                for (int mt = 0; mt < 4; mt++) {
                    uint32_t A[4];
                    LDM4(A, a_h + mt * 2048 + swA);
#pragma unroll
                    for (int nt = 0; nt < 8; nt++) {
                        const int np = nt >> 1, ix = nt & 1;
                        mma_f16(acc[mt][nt], A, Bh[np][ix], Bh[np][2 + ix]);
                    }
                }
            }

            if (c < 2) {
                CPA_WAIT0();
                __syncthreads();
            }
        }

        // prefetch next row chunk0 into buf p^1
        const int nbh = bh + GRID;
        if (nbh < NROWS) {
            STAGE_X(nbh >> 7, nbh & 127, 0, p ^ 1);
            CPA_COMMIT();
        }

        // ---- epilogue: bias + activation -> fp16 gates [m][276B]
#pragma unroll
        for (int mt = 0; mt < 4; mt++) {
            const uint32_t glo = smb + GATE_B +
                                 (uint32_t)(mw * 64 + mt * 16 + r) * GROW_B;
            const uint32_t ghi = glo + 8u * GROW_B;
#pragma unroll
            for (int nt = 0; nt < 8; nt++) {
                const uint32_t w2o = (uint32_t)(nw * 32 + nt * 4 + cl) * 4u;
                float v0 = acc[mt][nt][0] + blo[mt];
                float v1 = acc[mt][nt][1] + blo[mt];
                float v2 = acc[mt][nt][2] + bhi[mt];
                float v3 = acc[mt][nt][3] + bhi[mt];
                if (isg) {
                    v0 = tanh_f(v0); v1 = tanh_f(v1);
                    v2 = tanh_f(v2); v3 = tanh_f(v3);
                } else {
                    v0 = sigmoid_f(v0); v1 = sigmoid_f(v1);
                    v2 = sigmoid_f(v2); v3 = sigmoid_f(v3);
                }
                uint32_t p01, p23;
                asm("cvt.rn.f16x2.f32 %0, %1, %2;" : "=r"(p01) : "f"(v1), "f"(v0));
                asm("cvt.rn.f16x2.f32 %0, %1, %2;" : "=r"(p23) : "f"(v3), "f"(v2));
                sts32(glo + w2o, p01);
                sts32(ghi + w2o, p23);
            }
        }
        __syncthreads();

        // ---- LSTM scan: 8 seg x 16 w; two hc rows per thread; reg partials
        float cA0[16], PA0[16], cA1[16], PA1[16];
        {
            float c0 = 0.f, p0 = 1.f, c1 = 0.f, p1 = 1.f;
#pragma unroll
            for (int j = 0; j < 8; j++) {
                uint32_t iw0 = lds32(gsc0 + 4u * j);
                uint32_t fw0 = lds32(gsc0 + 4u * j + 64u * GROW_B);
                uint32_t gg0 = lds32(gsc0 + 4u * j + 192u * GROW_B);
                uint32_t iw1 = lds32(gsc1 + 4u * j);
                uint32_t fw1 = lds32(gsc1 + 4u * j + 64u * GROW_B);
                uint32_t gg1 = lds32(gsc1 + 4u * j + 192u * GROW_B);
                float2 iv0 = h2f2(iw0), fv0 = h2f2(fw0), gv0 = h2f2(gg0);
                float2 iv1 = h2f2(iw1), fv1 = h2f2(fw1), gv1 = h2f2(gg1);
                c0 = fmaf(fv0.x, c0, iv0.x * gv0.x); p0 *= fv0.x;
                cA0[2 * j] = c0; PA0[2 * j] = p0;
                c0 = fmaf(fv0.y, c0, iv0.y * gv0.y); p0 *= fv0.y;
                cA0[2 * j + 1] = c0; PA0[2 * j + 1] = p0;
                c1 = fmaf(fv1.x, c1, iv1.x * gv1.x); p1 *= fv1.x;
                cA1[2 * j] = c1; PA1[2 * j] = p1;
                c1 = fmaf(fv1.y, c1, iv1.y * gv1.y); p1 *= fv1.y;
                cA1[2 * j + 1] = c1; PA1[2 * j + 1] = p1;
            }
            uint32_t psa = smb + PS_B + (uint32_t)(seg * 64 + hcl) * 8;
            asm volatile("st.shared.v2.f32 [%0], {%1, %2};"
                         :: "r"(psa), "f"(p0), "f"(c0) : "memory");
            asm volatile("st.shared.v2.f32 [%0], {%1, %2};"
                         :: "r"(psa + 256u), "f"(p1), "f"(c1) : "memory");
        }
        __syncthreads();

        float cin0 = 0.f, cin1 = 0.f;
#pragma unroll
        for (int s2 = 0; s2 < 7; s2++) {
            if (s2 < seg) {
                uint32_t psa = smb + PS_B + (uint32_t)(s2 * 64 + hcl) * 8;
                float P0, S0, P1, S1;
                asm volatile("ld.shared.v2.f32 {%0, %1}, [%2];"
                             : "=f"(P0), "=f"(S0) : "r"(psa));
                asm volatile("ld.shared.v2.f32 {%0, %1}, [%2];"
                             : "=f"(P1), "=f"(S1) : "r"(psa + 256u));
                cin0 = fmaf(P0, cin0, S0);
                cin1 = fmaf(P1, cin1, S1);
            }
        }

        {
            float* po0 = out + ((size_t)(b * HCv + hcl) * Hv + h) * Wv + seg * 16;
            float* po1 = po0 + (size_t)32 * Hv * Wv;
            float q0[4], q1[4];
#pragma unroll
            for (int j = 0; j < 8; j++) {
                uint32_t ow0 = lds32(gsc0 + 4u * j + 128u * GROW_B);
                uint32_t ow1 = lds32(gsc1 + 4u * j + 128u * GROW_B);
                float2 ov0 = h2f2(ow0), ov1 = h2f2(ow1);
                float t00 = fmaf(PA0[2 * j], cin0, cA0[2 * j]);
                float t01 = fmaf(PA0[2 * j + 1], cin0, cA0[2 * j + 1]);
                float t10 = fmaf(PA1[2 * j], cin1, cA1[2 * j]);
                float t11 = fmaf(PA1[2 * j + 1], cin1, cA1[2 * j + 1]);
                q0[(2 * j) & 3] = ov0.x * tanh_f(t00);
                q0[(2 * j + 1) & 3] = ov0.y * tanh_f(t01);
                q1[(2 * j) & 3] = ov1.x * tanh_f(t10);
                q1[(2 * j + 1) & 3] = ov1.y * tanh_f(t11);
                if (j & 1) {
                    *reinterpret_cast<float4*>(po0 + (j >> 1) * 4) =
                        make_float4(q0[0], q0[1], q0[2], q0[3]);
                    *reinterpret_cast<float4*>(po1 + (j >> 1) * 4) =
                        make_float4(q1[0], q1[1], q1[2], q1[3]);
                }
            }
        }

        if (nbh < NROWS) CPA_WAIT0();
        __syncthreads();   // gates consumed; next-row X visible
        p ^= 1;
    }
}

extern "C" void kernel_launch(void* const* d_in, const int* in_sizes, int n_in,
                              void* d_out, int out_size) {
    const float* x    = (const float*)d_in[0];
    const float* wgt  = (const float*)d_in[1];
    const float* bias = (const float*)d_in[2];
    float* out = (float*)d_out;

    cudaFuncSetAttribute(rowlstm_fused,
                         cudaFuncAttributeMaxDynamicSharedMemorySize, SMEM_BYTES);

    prep_xw<<<8192, 256>>>(x, wgt);
    rowlstm_fused<<<GRID, 256, SMEM_BYTES>>>(bias, out);
}

// round 14
// speedup vs baseline: 1.0097x; 1.0097x over previous
#include <cuda_runtime.h>
#include <cuda_fp16.h>
#include <cstdint>

#define Bv 16
#define Cv 64
#define Hv 128
#define Wv 128
#define HCv 64
#define NROWS 2048
#define GRID 148

// Pre-baked W image (fp16): [chunk(3)][m(256)][k(64) octet-swizzled] = 96 KB
__device__ __align__(16) uint16_t g_wimg[3 * 256 * 64];
// Pre-rounded X plane (fp16), layout [b][ic][h][w]
#define XN ((size_t)Bv * Cv * Hv * Wv)
__device__ __align__(16) __half g_xhi[XN];

// ---- smem map (bytes) ----
// W resident: 3 x 32KB at 0
// XBUF: 2 x 24KB (96-k super-chunks) at 98304 .. 147456
// GATES fp16 at 147456: [m(256)][138 halves] (stride 276B = 69 words == 5 mod 32)
// PS (scan partials, fp32 pairs) at 218112 (4KB)
#define XBUF_B 98304
#define GATE_B 147456
#define GROW_B 276
#define PS_B   218112
#define SMEM_BYTES 222208

extern __shared__ uint32_t smw[];

__device__ __forceinline__ uint32_t smem_u32(const void* p) {
    uint32_t a;
    asm("{ .reg .u64 t; cvta.to.shared.u64 t, %1; cvt.u32.u64 %0, t; }"
        : "=r"(a) : "l"(p));
    return a;
}

__device__ __forceinline__ float tanh_f(float x) {
    float y;
    asm("tanh.approx.f32 %0, %1;" : "=f"(y) : "f"(x));
    return y;
}
__device__ __forceinline__ float sigmoid_f(float x) {
    return fmaf(tanh_f(0.5f * x), 0.5f, 0.5f);
}

__device__ __forceinline__ void mma_f16(float* c, const uint32_t* a,
                                        uint32_t b0, uint32_t b1) {
    asm volatile(
        "mma.sync.aligned.m16n8k16.row.col.f32.f16.f16.f32 "
        "{%0,%1,%2,%3}, {%4,%5,%6,%7}, {%8,%9}, {%0,%1,%2,%3};\n"
        : "+f"(c[0]), "+f"(c[1]), "+f"(c[2]), "+f"(c[3])
        : "r"(a[0]), "r"(a[1]), "r"(a[2]), "r"(a[3]), "r"(b0), "r"(b1));
}

#define LDM4(R, addr) \
    asm volatile("ldmatrix.sync.aligned.m8n8.x4.shared.b16 {%0,%1,%2,%3}, [%4];" \
        : "=r"((R)[0]), "=r"((R)[1]), "=r"((R)[2]), "=r"((R)[3]) : "r"(addr))
#define LDM4T(R, addr) \
    asm volatile("ldmatrix.sync.aligned.m8n8.x4.trans.shared.b16 {%0,%1,%2,%3}, [%4];" \
        : "=r"((R)[0]), "=r"((R)[1]), "=r"((R)[2]), "=r"((R)[3]) : "r"(addr))
#define CPA16(dst, src) \
    asm volatile("cp.async.ca.shared.global [%0], [%1], 16;" :: "r"(dst), "l"(src))
#define CPA16Z(dst, src, sz) \
    asm volatile("cp.async.ca.shared.global [%0], [%1], 16, %2;" \
                 :: "r"(dst), "l"(src), "r"(sz))
#define CPA_COMMIT() asm volatile("cp.async.commit_group;" ::: "memory")
#define CPA_WAIT0()  asm volatile("cp.async.wait_group 0;" ::: "memory")

__device__ __forceinline__ void sts32(uint32_t a, uint32_t v) {
    asm volatile("st.shared.u32 [%0], %1;" :: "r"(a), "r"(v) : "memory");
}
__device__ __forceinline__ uint32_t lds32(uint32_t a) {
    uint32_t v;
    asm volatile("ld.shared.u32 %0, [%1];" : "=r"(v) : "r"(a));
    return v;
}
__device__ __forceinline__ float2 h2f2(uint32_t w) {
    return __half22float2(*reinterpret_cast<__half2*>(&w));
}

// ---------------------------------------------------------------- prep kernel
__global__ void __launch_bounds__(256)
prep_xw(const float* __restrict__ x, const float* __restrict__ wgt) {
    if (blockIdx.x < 192) {
        int k = blockIdx.x;
        int m = threadIdx.x;
        float v = wgt[m * 192 + k];
        int c = k >> 6, kl = k & 63, o = kl >> 3, e = kl & 7;
        g_wimg[c * 16384 + m * 64 + (((o ^ (m & 7)) << 3) + e)] =
            __half_as_ushort(__float2half_rn(v));
    }
    size_t i = ((size_t)blockIdx.x * 256 + threadIdx.x) * 8;
    float4 a = *reinterpret_cast<const float4*>(x + i);
    float4 c = *reinterpret_cast<const float4*>(x + i + 4);
    float vf[8] = {a.x, a.y, a.z, a.w, c.x, c.y, c.z, c.w};
    uint32_t hw[4];
#pragma unroll
    for (int j = 0; j < 4; j++) {
        __half2 hh = __float22half2_rn(make_float2(vf[2 * j], vf[2 * j + 1]));
        hw[j] = *reinterpret_cast<uint32_t*>(&hh);
    }
    *reinterpret_cast<uint4*>(g_xhi + i) = make_uint4(hw[0], hw[1], hw[2], hw[3]);
}

// ---------------------------------------------------------------- persistent fused kernel
// 148 CTAs (1/SM), 512 threads = 16 warps (4m x 4n), warp tile 64m x 32w.
// W (96KB) resident; X staged as TWO 96-k super-chunks per row (24KB buffers);
// 4 syncs/row. fp16 gates; register-partial scan.
__global__ void __launch_bounds__(512, 1)
rowlstm_fused(const float* __restrict__ bias, float* __restrict__ out) {
    const int tid = threadIdx.x;
    const int lane = tid & 31;
    const int wid = tid >> 5;
    const int mw = wid & 3;
    const int nw = wid >> 2;
    const int r = lane >> 2, cl = lane & 3;

    const uint32_t smb = smem_u32(smw);

    const int l7 = lane & 7, l15 = lane & 15, lk = lane >> 4;
    const int krl = l7 + ((lane & 16) >> 1);
    const int wo = (lane >> 3) & 1;

    uint64_t gw, gxh;
    asm("cvta.to.global.u64 %0, %1;" : "=l"(gw) : "l"((const void*)g_wimg));
    asm("cvta.to.global.u64 %0, %1;" : "=l"(gxh) : "l"((const void*)g_xhi));

    float blo[4], bhi[4];
#pragma unroll
    for (int mt = 0; mt < 4; mt++) {
        blo[mt] = bias[mw * 64 + mt * 16 + r];
        bhi[mt] = bias[mw * 64 + mt * 16 + 8 + r];
    }
    const bool isg = (mw == 3);

    // scan mapping (row-invariant): 8 seg x 16 w, hc = tid & 63
    const int seg = tid >> 6;
    const int hc = tid & 63;
    const uint32_t gsc = smb + GATE_B + (uint32_t)hc * GROW_B + (uint32_t)seg * 32;

// stage a 96-k super-chunk (s = 0/1) for row (bb_,hh_) into buffer sb (0/1)
#define STAGE_X96(bb_, hh_, s, sb)                                          \
    do {                                                                    \
        _Pragma("unroll") for (int t = 0; t < 3; t++) {                     \
            int g = t * 512 + tid;                                          \
            int krow = g >> 4;                                              \
            int woct = g & 15;                                              \
            int kg = (s) * 96 + krow;                                       \
            int ic = kg / 3;                                                \
            int kh = kg - 3 * ic;                                           \
            int hp = (hh_) + kh - 2;                                        \
            int sz = (hp >= 0) ? 16 : 0;                                    \
            int hpc = (hp >= 0) ? hp : 0;                                   \
            size_t eoff = (((size_t)((bb_) * Cv + ic) * Hv + hpc) * Wv +    \
                           woct * 8) * 2;                                   \
            uint32_t dst = smb + XBUF_B + (sb) * 24576 + krow * 256 +       \
                           ((woct ^ (krow & 7)) << 4);                      \
            CPA16Z(dst, gxh + eoff, sz);                                    \
        }                                                                   \
    } while (0)

    // ---- preamble: W (96KB, once per SM) + first row super-A -> buf 0
    {
#pragma unroll
        for (int j = 0; j < 12; j++)
            CPA16(smb + tid * 16 + j * 8192, gw + tid * 16 + j * 8192);
        STAGE_X96(blockIdx.x >> 7, blockIdx.x & 127, 0, 0);
        CPA_COMMIT();
        CPA_WAIT0();
        __syncthreads();
    }

#pragma unroll 1
    for (int bh = blockIdx.x; bh < NROWS; bh += GRID) {
        const int b = bh >> 7, h = bh & 127;
        const int nbh = bh + GRID;

        float acc[4][4][4];
#pragma unroll
        for (int mt = 0; mt < 4; mt++)
#pragma unroll
            for (int nt = 0; nt < 4; nt++)
#pragma unroll
                for (int q = 0; q < 4; q++) acc[mt][nt][q] = 0.0f;

        // stage super-B (k 96..191) of this row into buf 1 (overlaps MMAs below)
        STAGE_X96(b, h, 1, 1);
        CPA_COMMIT();

        // B fragment bases (per super-buffer)
        uint32_t bb0[2], bb1[2];
#pragma unroll
        for (int np = 0; np < 2; np++) {
            int oct = ((nw * 32 + np * 16) >> 3) + wo;
            uint32_t sw = (uint32_t)((oct ^ l7) << 4) + (uint32_t)krl * 256;
            bb0[np] = smb + XBUF_B + sw;
            bb1[np] = smb + XBUF_B + 24576 + sw;
        }

// one global k-step (ksg = 0..11); buffer chosen by caller
#define KSTEP(ksg, bbx)                                                     \
    do {                                                                    \
        const int loc = (ksg) % 6;                                          \
        const int chunk = (ksg) >> 2;                                       \
        const int ksin = (ksg) & 3;                                         \
        uint32_t Bh[2][4];                                                  \
        _Pragma("unroll") for (int np = 0; np < 2; np++)                    \
            LDM4T(Bh[np], (bbx)[np] + loc * 4096);                          \
        const uint32_t a_h = smb + chunk * 32768 + (mw * 64 + l15) * 128;   \
        const uint32_t swA = (uint32_t)(((2 * ksin + lk) ^ l7) << 4);       \
        _Pragma("unroll") for (int mt = 0; mt < 4; mt++) {                  \
            uint32_t A[4];                                                  \
            LDM4(A, a_h + mt * 2048 + swA);                                 \
            _Pragma("unroll") for (int nt = 0; nt < 4; nt++) {              \
                const int np = nt >> 1, ix = nt & 1;                        \
                mma_f16(acc[mt][nt], A, Bh[np][ix], Bh[np][2 + ix]);        \
            }                                                               \
        }                                                                   \
    } while (0)

        // ---- super 0: 6 uninterrupted k-steps from buf 0
#pragma unroll
        for (int ksg = 0; ksg < 6; ksg++) KSTEP(ksg, bb0);

        CPA_WAIT0();        // super-B arrived
        __syncthreads();    // (also: all buf-0 reads done)

        // prefetch next row's super-A into buf 0 (overlaps super-1 MMAs + tail)
        if (nbh < NROWS) {
            STAGE_X96(nbh >> 7, nbh & 127, 0, 0);
            CPA_COMMIT();
        }

        // ---- super 1: 6 uninterrupted k-steps from buf 1
#pragma unroll
        for (int ksg = 6; ksg < 12; ksg++) KSTEP(ksg, bb1);

        // ---- epilogue: bias + activation -> fp16 gates [m][276B]
#pragma unroll
        for (int mt = 0; mt < 4; mt++) {
            const uint32_t glo = smb + GATE_B +
                                 (uint32_t)(mw * 64 + mt * 16 + r) * GROW_B;
            const uint32_t ghi = glo + 8u * GROW_B;
#pragma unroll
            for (int nt = 0; nt < 4; nt++) {
                const uint32_t w2o = (uint32_t)(nw * 16 + nt * 4 + cl) * 4u;
                float v0 = acc[mt][nt][0] + blo[mt];
                float v1 = acc[mt][nt][1] + blo[mt];
                float v2 = acc[mt][nt][2] + bhi[mt];
                float v3 = acc[mt][nt][3] + bhi[mt];
                if (isg) {
                    v0 = tanh_f(v0); v1 = tanh_f(v1);
                    v2 = tanh_f(v2); v3 = tanh_f(v3);
                } else {
                    v0 = sigmoid_f(v0); v1 = sigmoid_f(v1);
                    v2 = sigmoid_f(v2); v3 = sigmoid_f(v3);
                }
                uint32_t p01, p23;
                asm("cvt.rn.f16x2.f32 %0, %1, %2;" : "=r"(p01) : "f"(v1), "f"(v0));
                asm("cvt.rn.f16x2.f32 %0, %1, %2;" : "=r"(p23) : "f"(v3), "f"(v2));
                sts32(glo + w2o, p01);
                sts32(ghi + w2o, p23);
            }
        }
        __syncthreads();

        // ---- LSTM scan: 8 seg x 16 w; partials in registers
        float cA[16], PA[16];
        {
            float cc = 0.f, pp = 1.f;
#pragma unroll
            for (int j = 0; j < 8; j++) {
                uint32_t iw = lds32(gsc + 4u * j);
                uint32_t fw = lds32(gsc + 4u * j + 64u * GROW_B);
                uint32_t gg = lds32(gsc + 4u * j + 192u * GROW_B);
                float2 iv = h2f2(iw), fv = h2f2(fw), gv = h2f2(gg);
                cc = fmaf(fv.x, cc, iv.x * gv.x); pp *= fv.x;
                cA[2 * j] = cc; PA[2 * j] = pp;
                cc = fmaf(fv.y, cc, iv.y * gv.y); pp *= fv.y;
                cA[2 * j + 1] = cc; PA[2 * j + 1] = pp;
            }
            uint32_t psa = smb + PS_B + (uint32_t)(seg * 64 + hc) * 8;
            asm volatile("st.shared.v2.f32 [%0], {%1, %2};"
                         :: "r"(psa), "f"(pp), "f"(cc) : "memory");
        }
        __syncthreads();

        float cin = 0.f;
#pragma unroll
        for (int s2 = 0; s2 < 7; s2++) {
            if (s2 < seg) {
                uint32_t psa = smb + PS_B + (uint32_t)(s2 * 64 + hc) * 8;
                float P, S;
                asm volatile("ld.shared.v2.f32 {%0, %1}, [%2];"
                             : "=f"(P), "=f"(S) : "r"(psa));
                cin = fmaf(P, cin, S);
            }
        }

        {
            float hv[16];
#pragma unroll
            for (int j = 0; j < 8; j++) {
                uint32_t ow = lds32(gsc + 4u * j + 128u * GROW_B);
                float2 ov = h2f2(ow);
                float t0 = fmaf(PA[2 * j], cin, cA[2 * j]);
                float t1 = fmaf(PA[2 * j + 1], cin, cA[2 * j + 1]);
                hv[2 * j] = ov.x * tanh_f(t0);
                hv[2 * j + 1] = ov.y * tanh_f(t1);
            }
            float* po = out + ((size_t)(b * HCv + hc) * Hv + h) * Wv + seg * 16;
            *reinterpret_cast<float4*>(po) =
                make_float4(hv[0], hv[1], hv[2], hv[3]);
            *reinterpret_cast<float4*>(po + 4) =
                make_float4(hv[4], hv[5], hv[6], hv[7]);
            *reinterpret_cast<float4*>(po + 8) =
                make_float4(hv[8], hv[9], hv[10], hv[11]);
            *reinterpret_cast<float4*>(po + 12) =
                make_float4(hv[12], hv[13], hv[14], hv[15]);
        }

        if (nbh < NROWS) CPA_WAIT0();
        __syncthreads();   // next-row super-A visible; gates/PS reusable
    }
}

extern "C" void kernel_launch(void* const* d_in, const int* in_sizes, int n_in,
                              void* d_out, int out_size) {
    const float* x    = (const float*)d_in[0];
    const float* wgt  = (const float*)d_in[1];
    const float* bias = (const float*)d_in[2];
    float* out = (float*)d_out;

    cudaFuncSetAttribute(rowlstm_fused,
                         cudaFuncAttributeMaxDynamicSharedMemorySize, SMEM_BYTES);

    prep_xw<<<8192, 256>>>(x, wgt);
    rowlstm_fused<<<GRID, 512, SMEM_BYTES>>>(bias, out);
}

// round 15
// speedup vs baseline: 1.0597x; 1.0495x over previous
#include <cuda_runtime.h>
#include <cuda_fp16.h>
#include <cstdint>

#define Bv 16
#define Cv 64
#define Hv 128
#define Wv 128
#define HCv 64
#define NROWS 2048
#define GRID 148

// Pre-baked W image (fp16): [chunk(3)][m(256)][k(64) octet-swizzled] = 96 KB
__device__ __align__(16) uint16_t g_wimg[3 * 256 * 64];
// Pre-rounded X plane (fp16), layout [b][ic][h][w]
#define XN ((size_t)Bv * Cv * Hv * Wv)
__device__ __align__(16) __half g_xhi[XN];

// ---- smem map (bytes) ----
// W resident: 3 x 32KB at 0
// XBUF: 2 x 24KB (96-k super-chunks) at 98304 .. 147456
// GATES fp16 at 147456: [m(256)][138 halves] (stride 276B = 69 words == 5 mod 32)
// PS (scan partials, fp32 pairs) at 218112 (4KB)
#define XBUF_B 98304
#define GATE_B 147456
#define GROW_B 276
#define PS_B   218112
#define SMEM_BYTES 222208

extern __shared__ uint32_t smw[];

__device__ __forceinline__ uint32_t smem_u32(const void* p) {
    uint32_t a;
    asm("{ .reg .u64 t; cvta.to.shared.u64 t, %1; cvt.u32.u64 %0, t; }"
        : "=r"(a) : "l"(p));
    return a;
}

__device__ __forceinline__ float tanh_f(float x) {
    float y;
    asm("tanh.approx.f32 %0, %1;" : "=f"(y) : "f"(x));
    return y;
}
__device__ __forceinline__ float sigmoid_f(float x) {
    return fmaf(tanh_f(0.5f * x), 0.5f, 0.5f);
}

__device__ __forceinline__ void mma_f16(float* c, const uint32_t* a,
                                        uint32_t b0, uint32_t b1) {
    asm volatile(
        "mma.sync.aligned.m16n8k16.row.col.f32.f16.f16.f32 "
        "{%0,%1,%2,%3}, {%4,%5,%6,%7}, {%8,%9}, {%0,%1,%2,%3};\n"
        : "+f"(c[0]), "+f"(c[1]), "+f"(c[2]), "+f"(c[3])
        : "r"(a[0]), "r"(a[1]), "r"(a[2]), "r"(a[3]), "r"(b0), "r"(b1));
}

#define LDM4(R, addr) \
    asm volatile("ldmatrix.sync.aligned.m8n8.x4.shared.b16 {%0,%1,%2,%3}, [%4];" \
        : "=r"((R)[0]), "=r"((R)[1]), "=r"((R)[2]), "=r"((R)[3]) : "r"(addr))
#define LDM4T(R, addr) \
    asm volatile("ldmatrix.sync.aligned.m8n8.x4.trans.shared.b16 {%0,%1,%2,%3}, [%4];" \
        : "=r"((R)[0]), "=r"((R)[1]), "=r"((R)[2]), "=r"((R)[3]) : "r"(addr))
#define CPA16(dst, src) \
    asm volatile("cp.async.ca.shared.global [%0], [%1], 16;" :: "r"(dst), "l"(src))
#define CPA16Z(dst, src, sz) \
    asm volatile("cp.async.ca.shared.global [%0], [%1], 16, %2;" \
                 :: "r"(dst), "l"(src), "r"(sz))
#define CPA_COMMIT() asm volatile("cp.async.commit_group;" ::: "memory")
#define CPA_WAIT0()  asm volatile("cp.async.wait_group 0;" ::: "memory")

__device__ __forceinline__ void sts32(uint32_t a, uint32_t v) {
    asm volatile("st.shared.u32 [%0], %1;" :: "r"(a), "r"(v) : "memory");
}
__device__ __forceinline__ uint32_t lds32(uint32_t a) {
    uint32_t v;
    asm volatile("ld.shared.u32 %0, [%1];" : "=r"(v) : "r"(a));
    return v;
}
__device__ __forceinline__ float2 h2f2(uint32_t w) {
    return __half22float2(*reinterpret_cast<__half2*>(&w));
}

// ---------------------------------------------------------------- prep kernel
__global__ void __launch_bounds__(256)
prep_xw(const float* __restrict__ x, const float* __restrict__ wgt) {
    if (blockIdx.x < 192) {
        int k = blockIdx.x;
        int m = threadIdx.x;
        float v = wgt[m * 192 + k];
        int c = k >> 6, kl = k & 63, o = kl >> 3, e = kl & 7;
        g_wimg[c * 16384 + m * 64 + (((o ^ (m & 7)) << 3) + e)] =
            __half_as_ushort(__float2half_rn(v));
    }
    size_t i = ((size_t)blockIdx.x * 256 + threadIdx.x) * 8;
    float4 a = *reinterpret_cast<const float4*>(x + i);
    float4 c = *reinterpret_cast<const float4*>(x + i + 4);
    float vf[8] = {a.x, a.y, a.z, a.w, c.x, c.y, c.z, c.w};
    uint32_t hw[4];
#pragma unroll
    for (int j = 0; j < 4; j++) {
        __half2 hh = __float22half2_rn(make_float2(vf[2 * j], vf[2 * j + 1]));
        hw[j] = *reinterpret_cast<uint32_t*>(&hh);
    }
    *reinterpret_cast<uint4*>(g_xhi + i) = make_uint4(hw[0], hw[1], hw[2], hw[3]);
}

// ---------------------------------------------------------------- persistent fused kernel
// 148 CTAs (1/SM), 512 threads = 16 warps (4m x 4n), warp tile 64m x 32w.
// Pipelined: GEMM of row n interleaved (textually) with LSTM scan of row n-1.
// Scan is register-light: pass1 keeps only running (c,P); pass3 re-runs the
// recurrence from smem gates seeded with the true incoming c.
__global__ void __launch_bounds__(512, 1)
rowlstm_fused(const float* __restrict__ bias, float* __restrict__ out) {
    const int tid = threadIdx.x;
    const int lane = tid & 31;
    const int wid = tid >> 5;
    const int mw = wid & 3;
    const int nw = wid >> 2;
    const int r = lane >> 2, cl = lane & 3;

    const uint32_t smb = smem_u32(smw);

    const int l7 = lane & 7, l15 = lane & 15, lk = lane >> 4;
    const int krl = l7 + ((lane & 16) >> 1);
    const int wo = (lane >> 3) & 1;

    uint64_t gw, gxh;
    asm("cvta.to.global.u64 %0, %1;" : "=l"(gw) : "l"((const void*)g_wimg));
    asm("cvta.to.global.u64 %0, %1;" : "=l"(gxh) : "l"((const void*)g_xhi));

    float blo[4], bhi[4];
#pragma unroll
    for (int mt = 0; mt < 4; mt++) {
        blo[mt] = bias[mw * 64 + mt * 16 + r];
        bhi[mt] = bias[mw * 64 + mt * 16 + 8 + r];
    }
    const bool isg = (mw == 3);

    // scan mapping (row-invariant): 8 seg x 16 w, hc = tid & 63
    const int seg = tid >> 6;
    const int hc = tid & 63;
    const uint32_t gsc = smb + GATE_B + (uint32_t)hc * GROW_B + (uint32_t)seg * 32;
    const uint32_t psme = smb + PS_B + (uint32_t)(seg * 64 + hc) * 8;

#define STAGE_X96(bb_, hh_, s, sb)                                          \
    do {                                                                    \
        _Pragma("unroll") for (int t = 0; t < 3; t++) {                     \
            int g = t * 512 + tid;                                          \
            int krow = g >> 4;                                              \
            int woct = g & 15;                                              \
            int kg = (s) * 96 + krow;                                       \
            int ic = kg / 3;                                                \
            int kh = kg - 3 * ic;                                           \
            int hp = (hh_) + kh - 2;                                        \
            int sz = (hp >= 0) ? 16 : 0;                                    \
            int hpc = (hp >= 0) ? hp : 0;                                   \
            size_t eoff = (((size_t)((bb_) * Cv + ic) * Hv + hpc) * Wv +    \
                           woct * 8) * 2;                                   \
            uint32_t dst = smb + XBUF_B + (sb) * 24576 + krow * 256 +       \
                           ((woct ^ (krow & 7)) << 4);                      \
            CPA16Z(dst, gxh + eoff, sz);                                    \
        }                                                                   \
    } while (0)

// one global k-step (ksg = 0..11)
#define KSTEP(ksg, bbx)                                                     \
    do {                                                                    \
        const int loc = (ksg) % 6;                                          \
        const int chunk = (ksg) >> 2;                                       \
        const int ksin = (ksg) & 3;                                         \
        uint32_t Bh[2][4];                                                  \
        _Pragma("unroll") for (int np = 0; np < 2; np++)                    \
            LDM4T(Bh[np], (bbx)[np] + loc * 4096);                          \
        const uint32_t a_h = smb + chunk * 32768 + (mw * 64 + l15) * 128;   \
        const uint32_t swA = (uint32_t)(((2 * ksin + lk) ^ l7) << 4);       \
        _Pragma("unroll") for (int mt = 0; mt < 4; mt++) {                  \
            uint32_t A[4];                                                  \
            LDM4(A, a_h + mt * 2048 + swA);                                 \
            _Pragma("unroll") for (int nt = 0; nt < 4; nt++) {              \
                const int np = nt >> 1, ix = nt & 1;                        \
                mma_f16(acc[mt][nt], A, Bh[np][ix], Bh[np][2 + ix]);        \
            }                                                               \
        }                                                                   \
    } while (0)

// scan pass1 step j (prev row): running (sc, sp)
#define SCAN_P1(j)                                                          \
    if (hasprv) {                                                           \
        uint32_t iw = lds32(gsc + 4u * (j));                                \
        uint32_t fw = lds32(gsc + 4u * (j) + 64u * GROW_B);                 \
        uint32_t gg = lds32(gsc + 4u * (j) + 192u * GROW_B);                \
        float2 iv = h2f2(iw), fv = h2f2(fw), gv = h2f2(gg);                 \
        sc = fmaf(fv.x, sc, iv.x * gv.x); sp *= fv.x;                       \
        sc = fmaf(fv.y, sc, iv.y * gv.y); sp *= fv.y;                       \
    }

// scan pass3 step j (prev row): direct recurrence seeded with true cin
#define SCAN_P3(j)                                                          \
    if (hasprv) {                                                           \
        uint32_t iw = lds32(gsc + 4u * (j));                                \
        uint32_t fw = lds32(gsc + 4u * (j) + 64u * GROW_B);                 \
        uint32_t ow = lds32(gsc + 4u * (j) + 128u * GROW_B);                \
        uint32_t gg = lds32(gsc + 4u * (j) + 192u * GROW_B);                \
        float2 iv = h2f2(iw), fv = h2f2(fw), ov = h2f2(ow), gv = h2f2(gg);  \
        c3 = fmaf(fv.x, c3, iv.x * gv.x);                                   \
        q[((j) & 1) * 2]     = ov.x * tanh_f(c3);                           \
        c3 = fmaf(fv.y, c3, iv.y * gv.y);                                   \
        q[((j) & 1) * 2 + 1] = ov.y * tanh_f(c3);                           \
        if ((j) & 1)                                                        \
            *reinterpret_cast<float4*>(po + ((j) >> 1) * 4) =               \
                make_float4(q[0], q[1], q[2], q[3]);                        \
    }

#define SCAN_P2()                                                           \
    do {                                                                    \
        cin = 0.f;                                                          \
        if (hasprv) {                                                       \
            _Pragma("unroll") for (int s2 = 0; s2 < 7; s2++) {              \
                if (s2 < seg) {                                             \
                    uint32_t psa = smb + PS_B + (uint32_t)(s2 * 64 + hc) * 8; \
                    float P, S;                                             \
                    asm volatile("ld.shared.v2.f32 {%0, %1}, [%2];"         \
                                 : "=f"(P), "=f"(S) : "r"(psa));            \
                    cin = fmaf(P, cin, S);                                  \
                }                                                           \
            }                                                               \
        }                                                                   \
    } while (0)

    // ---- preamble: W (96KB, once per SM) + first row super-A -> buf 0
    {
#pragma unroll
        for (int j = 0; j < 12; j++)
            CPA16(smb + tid * 16 + j * 8192, gw + tid * 16 + j * 8192);
        STAGE_X96(blockIdx.x >> 7, blockIdx.x & 127, 0, 0);
        CPA_COMMIT();
        CPA_WAIT0();
        __syncthreads();
    }

    // B fragment bases (fixed)
    uint32_t bb0[2], bb1[2];
#pragma unroll
    for (int np = 0; np < 2; np++) {
        int oct = ((nw * 32 + np * 16) >> 3) + wo;
        uint32_t sw = (uint32_t)((oct ^ l7) << 4) + (uint32_t)krl * 256;
        bb0[np] = smb + XBUF_B + sw;
        bb1[np] = smb + XBUF_B + 24576 + sw;
    }

#pragma unroll 1
    for (int bh = blockIdx.x; bh < NROWS; bh += GRID) {
        const int b = bh >> 7, h = bh & 127;
        const int nbh = bh + GRID;
        const bool hasprv = (bh != (int)blockIdx.x);
        const int pbh = bh - GRID;
        float* po = out + ((size_t)(((pbh >> 7) & 15) * HCv + hc) * Hv +
                           (pbh & 127)) * Wv + seg * 16;

        float acc[4][4][4];
#pragma unroll
        for (int mt = 0; mt < 4; mt++)
#pragma unroll
            for (int nt = 0; nt < 4; nt++)
#pragma unroll
                for (int q2 = 0; q2 < 4; q2++) acc[mt][nt][q2] = 0.0f;

        // stage super-B of this row into buf 1 (overlaps super-0 MMAs)
        STAGE_X96(b, h, 1, 1);
        CPA_COMMIT();

        float sc = 0.f, sp = 1.f, c3, cin;
        float q[4];

        // ---- super 0 (buf0) + scan pass1 of prev row, interleaved
        KSTEP(0, bb0); SCAN_P1(0);
        KSTEP(1, bb0); SCAN_P1(1);
        KSTEP(2, bb0); SCAN_P1(2); SCAN_P1(3);
        KSTEP(3, bb0); SCAN_P1(4);
        KSTEP(4, bb0); SCAN_P1(5); SCAN_P1(6);
        KSTEP(5, bb0); SCAN_P1(7);

        if (hasprv)
            asm volatile("st.shared.v2.f32 [%0], {%1, %2};"
                         :: "r"(psme), "f"(sp), "f"(sc) : "memory");

        CPA_WAIT0();        // super-B arrived
        __syncthreads();    // buf0 reads done + PS visible

        // prefetch next row's super-A into buf 0
        if (nbh < NROWS) {
            STAGE_X96(nbh >> 7, nbh & 127, 0, 0);
            CPA_COMMIT();
        }

        SCAN_P2();
        c3 = cin;

        // ---- super 1 (buf1) + scan pass3 of prev row, interleaved
        KSTEP(6, bb1);  SCAN_P3(0);
        KSTEP(7, bb1);  SCAN_P3(1); SCAN_P3(2);
        KSTEP(8, bb1);  SCAN_P3(3);
        KSTEP(9, bb1);  SCAN_P3(4); SCAN_P3(5);
        KSTEP(10, bb1); SCAN_P3(6);
        KSTEP(11, bb1); SCAN_P3(7);

        __syncthreads();   // pass3 reads done before gates overwrite

        // ---- epilogue: bias + activation -> fp16 gates [m][276B]
#pragma unroll
        for (int mt = 0; mt < 4; mt++) {
            const uint32_t glo = smb + GATE_B +
                                 (uint32_t)(mw * 64 + mt * 16 + r) * GROW_B;
            const uint32_t ghi = glo + 8u * GROW_B;
#pragma unroll
            for (int nt = 0; nt < 4; nt++) {
                const uint32_t w2o = (uint32_t)(nw * 16 + nt * 4 + cl) * 4u;
                float v0 = acc[mt][nt][0] + blo[mt];
                float v1 = acc[mt][nt][1] + blo[mt];
                float v2 = acc[mt][nt][2] + bhi[mt];
                float v3 = acc[mt][nt][3] + bhi[mt];
                if (isg) {
                    v0 = tanh_f(v0); v1 = tanh_f(v1);
                    v2 = tanh_f(v2); v3 = tanh_f(v3);
                } else {
                    v0 = sigmoid_f(v0); v1 = sigmoid_f(v1);
                    v2 = sigmoid_f(v2); v3 = sigmoid_f(v3);
                }
                uint32_t p01, p23;
                asm("cvt.rn.f16x2.f32 %0, %1, %2;" : "=r"(p01) : "f"(v1), "f"(v0));
                asm("cvt.rn.f16x2.f32 %0, %1, %2;" : "=r"(p23) : "f"(v3), "f"(v2));
                sts32(glo + w2o, p01);
                sts32(ghi + w2o, p23);
            }
        }

        if (nbh < NROWS) CPA_WAIT0();
        __syncthreads();   // gates visible for next iter's pass1; buf0 ready
    }

    // ---- tail: scan of the last row (non-interleaved)
    {
        const bool hasprv = true;
        const int lbh = (int)blockIdx.x +
                        ((NROWS - 1 - (int)blockIdx.x) / GRID) * GRID;
        float* po = out + ((size_t)(((lbh >> 7) & 15) * HCv + hc) * Hv +
                           (lbh & 127)) * Wv + seg * 16;
        float sc = 0.f, sp = 1.f, c3, cin;
        float q[4];
        SCAN_P1(0); SCAN_P1(1); SCAN_P1(2); SCAN_P1(3);
        SCAN_P1(4); SCAN_P1(5); SCAN_P1(6); SCAN_P1(7);
        asm volatile("st.shared.v2.f32 [%0], {%1, %2};"
                     :: "r"(psme), "f"(sp), "f"(sc) : "memory");
        __syncthreads();
        SCAN_P2();
        c3 = cin;
        SCAN_P3(0); SCAN_P3(1); SCAN_P3(2); SCAN_P3(3);
        SCAN_P3(4); SCAN_P3(5); SCAN_P3(6); SCAN_P3(7);
    }
}

extern "C" void kernel_launch(void* const* d_in, const int* in_sizes, int n_in,
                              void* d_out, int out_size) {
    const float* x    = (const float*)d_in[0];
    const float* wgt  = (const float*)d_in[1];
    const float* bias = (const float*)d_in[2];
    float* out = (float*)d_out;

    cudaFuncSetAttribute(rowlstm_fused,
                         cudaFuncAttributeMaxDynamicSharedMemorySize, SMEM_BYTES);

    prep_xw<<<8192, 256>>>(x, wgt);
    rowlstm_fused<<<GRID, 512, SMEM_BYTES>>>(bias, out);
}

// round 16
// speedup vs baseline: 1.0679x; 1.0077x over previous
#include <cuda_runtime.h>
#include <cuda_fp16.h>
#include <cstdint>

#define Bv 16
#define Cv 64
#define Hv 128
#define Wv 128
#define HCv 64
#define NROWS 2048
#define GRID 148

// Pre-baked W image (fp16): [chunk(3)][m(256)][k(64) octet-swizzled] = 96 KB
__device__ __align__(16) uint16_t g_wimg[3 * 256 * 64];
// Pre-rounded X plane (fp16), layout [b][ic][h][w]
#define XN ((size_t)Bv * Cv * Hv * Wv)
__device__ __align__(16) __half g_xhi[XN];

// ---- smem map (bytes) ----
// W resident: 3 x 32KB at 0
// XBUF: 2 x 24KB (96-k super-chunks) at 98304 .. 147456
// GATES fp16 at 147456: [m(256)][138 halves] (stride 276B = 69 words == 5 mod 32)
// PS (scan partials, fp32 pairs) at 218112 (4KB)
#define XBUF_B 98304
#define GATE_B 147456
#define GROW_B 276
#define PS_B   218112
#define SMEM_BYTES 222208

extern __shared__ uint32_t smw[];

__device__ __forceinline__ uint32_t smem_u32(const void* p) {
    uint32_t a;
    asm("{ .reg .u64 t; cvta.to.shared.u64 t, %1; cvt.u32.u64 %0, t; }"
        : "=r"(a) : "l"(p));
    return a;
}

__device__ __forceinline__ float tanh_f(float x) {
    float y;
    asm("tanh.approx.f32 %0, %1;" : "=f"(y) : "f"(x));
    return y;
}
__device__ __forceinline__ float sigmoid_f(float x) {
    return fmaf(tanh_f(0.5f * x), 0.5f, 0.5f);
}

// fp16-accumulator MMA: D(fp16x2 pair) = A*B + C
__device__ __forceinline__ void mma_f16acc(uint32_t* c, const uint32_t* a,
                                           uint32_t b0, uint32_t b1) {
    asm volatile(
        "mma.sync.aligned.m16n8k16.row.col.f16.f16.f16.f16 "
        "{%0,%1}, {%2,%3,%4,%5}, {%6,%7}, {%0,%1};\n"
        : "+r"(c[0]), "+r"(c[1])
        : "r"(a[0]), "r"(a[1]), "r"(a[2]), "r"(a[3]), "r"(b0), "r"(b1));
}

#define LDM4(R, addr) \
    asm volatile("ldmatrix.sync.aligned.m8n8.x4.shared.b16 {%0,%1,%2,%3}, [%4];" \
        : "=r"((R)[0]), "=r"((R)[1]), "=r"((R)[2]), "=r"((R)[3]) : "r"(addr))
#define LDM4T(R, addr) \
    asm volatile("ldmatrix.sync.aligned.m8n8.x4.trans.shared.b16 {%0,%1,%2,%3}, [%4];" \
        : "=r"((R)[0]), "=r"((R)[1]), "=r"((R)[2]), "=r"((R)[3]) : "r"(addr))
#define CPA16(dst, src) \
    asm volatile("cp.async.ca.shared.global [%0], [%1], 16;" :: "r"(dst), "l"(src))
#define CPA16Z(dst, src, sz) \
    asm volatile("cp.async.ca.shared.global [%0], [%1], 16, %2;" \
                 :: "r"(dst), "l"(src), "r"(sz))
#define CPA_COMMIT() asm volatile("cp.async.commit_group;" ::: "memory")
#define CPA_WAIT0()  asm volatile("cp.async.wait_group 0;" ::: "memory")

__device__ __forceinline__ void sts32(uint32_t a, uint32_t v) {
    asm volatile("st.shared.u32 [%0], %1;" :: "r"(a), "r"(v) : "memory");
}
__device__ __forceinline__ uint32_t lds32(uint32_t a) {
    uint32_t v;
    asm volatile("ld.shared.u32 %0, [%1];" : "=r"(v) : "r"(a));
    return v;
}
__device__ __forceinline__ float2 h2f2(uint32_t w) {
    return __half22float2(*reinterpret_cast<__half2*>(&w));
}

// ---------------------------------------------------------------- prep kernel
__global__ void __launch_bounds__(256)
prep_xw(const float* __restrict__ x, const float* __restrict__ wgt) {
    if (blockIdx.x < 192) {
        int k = blockIdx.x;
        int m = threadIdx.x;
        float v = wgt[m * 192 + k];
        int c = k >> 6, kl = k & 63, o = kl >> 3, e = kl & 7;
        g_wimg[c * 16384 + m * 64 + (((o ^ (m & 7)) << 3) + e)] =
            __half_as_ushort(__float2half_rn(v));
    }
    size_t i = ((size_t)blockIdx.x * 256 + threadIdx.x) * 8;
    float4 a = *reinterpret_cast<const float4*>(x + i);
    float4 c = *reinterpret_cast<const float4*>(x + i + 4);
    float vf[8] = {a.x, a.y, a.z, a.w, c.x, c.y, c.z, c.w};
    uint32_t hw[4];
#pragma unroll
    for (int j = 0; j < 4; j++) {
        __half2 hh = __float22half2_rn(make_float2(vf[2 * j], vf[2 * j + 1]));
        hw[j] = *reinterpret_cast<uint32_t*>(&hh);
    }
    *reinterpret_cast<uint4*>(g_xhi + i) = make_uint4(hw[0], hw[1], hw[2], hw[3]);
}

// ---------------------------------------------------------------- persistent fused kernel
// 148 CTAs (1/SM), 512 threads = 16 warps (4m x 4n), warp tile 64m x 32w.
// fp16 accumulators (single rounding per MMA chain step). GEMM of row n
// interleaved with LSTM scan of row n-1 (register-light scan).
__global__ void __launch_bounds__(512, 1)
rowlstm_fused(const float* __restrict__ bias, float* __restrict__ out) {
    const int tid = threadIdx.x;
    const int lane = tid & 31;
    const int wid = tid >> 5;
    const int mw = wid & 3;
    const int nw = wid >> 2;
    const int r = lane >> 2, cl = lane & 3;

    const uint32_t smb = smem_u32(smw);

    const int l7 = lane & 7, l15 = lane & 15, lk = lane >> 4;
    const int krl = l7 + ((lane & 16) >> 1);
    const int wo = (lane >> 3) & 1;

    uint64_t gw, gxh;
    asm("cvta.to.global.u64 %0, %1;" : "=l"(gw) : "l"((const void*)g_wimg));
    asm("cvta.to.global.u64 %0, %1;" : "=l"(gxh) : "l"((const void*)g_xhi));

    float blo[4], bhi[4];
#pragma unroll
    for (int mt = 0; mt < 4; mt++) {
        blo[mt] = bias[mw * 64 + mt * 16 + r];
        bhi[mt] = bias[mw * 64 + mt * 16 + 8 + r];
    }
    const bool isg = (mw == 3);

    // scan mapping (row-invariant): 8 seg x 16 w, hc = tid & 63
    const int seg = tid >> 6;
    const int hc = tid & 63;
    const uint32_t gsc = smb + GATE_B + (uint32_t)hc * GROW_B + (uint32_t)seg * 32;
    const uint32_t psme = smb + PS_B + (uint32_t)(seg * 64 + hc) * 8;

#define STAGE_X96(bb_, hh_, s, sb)                                          \
    do {                                                                    \
        _Pragma("unroll") for (int t = 0; t < 3; t++) {                     \
            int g = t * 512 + tid;                                          \
            int krow = g >> 4;                                              \
            int woct = g & 15;                                              \
            int kg = (s) * 96 + krow;                                       \
            int ic = kg / 3;                                                \
            int kh = kg - 3 * ic;                                           \
            int hp = (hh_) + kh - 2;                                        \
            int sz = (hp >= 0) ? 16 : 0;                                    \
            int hpc = (hp >= 0) ? hp : 0;                                   \
            size_t eoff = (((size_t)((bb_) * Cv + ic) * Hv + hpc) * Wv +    \
                           woct * 8) * 2;                                   \
            uint32_t dst = smb + XBUF_B + (sb) * 24576 + krow * 256 +       \
                           ((woct ^ (krow & 7)) << 4);                      \
            CPA16Z(dst, gxh + eoff, sz);                                    \
        }                                                                   \
    } while (0)

// one global k-step (ksg = 0..11)
#define KSTEP(ksg, bbx)                                                     \
    do {                                                                    \
        const int loc = (ksg) % 6;                                          \
        const int chunk = (ksg) >> 2;                                       \
        const int ksin = (ksg) & 3;                                         \
        uint32_t Bh[2][4];                                                  \
        _Pragma("unroll") for (int np = 0; np < 2; np++)                    \
            LDM4T(Bh[np], (bbx)[np] + loc * 4096);                          \
        const uint32_t a_h = smb + chunk * 32768 + (mw * 64 + l15) * 128;   \
        const uint32_t swA = (uint32_t)(((2 * ksin + lk) ^ l7) << 4);       \
        _Pragma("unroll") for (int mt = 0; mt < 4; mt++) {                  \
            uint32_t A[4];                                                  \
            LDM4(A, a_h + mt * 2048 + swA);                                 \
            _Pragma("unroll") for (int nt = 0; nt < 4; nt++) {              \
                const int np = nt >> 1, ix = nt & 1;                        \
                mma_f16acc(acc[mt][nt], A, Bh[np][ix], Bh[np][2 + ix]);     \
            }                                                               \
        }                                                                   \
    } while (0)

// scan pass1 step j (prev row): running (sc, sp)
#define SCAN_P1(j)                                                          \
    if (hasprv) {                                                           \
        uint32_t iw = lds32(gsc + 4u * (j));                                \
        uint32_t fw = lds32(gsc + 4u * (j) + 64u * GROW_B);                 \
        uint32_t gg = lds32(gsc + 4u * (j) + 192u * GROW_B);                \
        float2 iv = h2f2(iw), fv = h2f2(fw), gv = h2f2(gg);                 \
        sc = fmaf(fv.x, sc, iv.x * gv.x); sp *= fv.x;                       \
        sc = fmaf(fv.y, sc, iv.y * gv.y); sp *= fv.y;                       \
    }

// scan pass3 step j (prev row): direct recurrence seeded with true cin
#define SCAN_P3(j)                                                          \
    if (hasprv) {                                                           \
        uint32_t iw = lds32(gsc + 4u * (j));                                \
        uint32_t fw = lds32(gsc + 4u * (j) + 64u * GROW_B);                 \
        uint32_t ow = lds32(gsc + 4u * (j) + 128u * GROW_B);                \
        uint32_t gg = lds32(gsc + 4u * (j) + 192u * GROW_B);                \
        float2 iv = h2f2(iw), fv = h2f2(fw), ov = h2f2(ow), gv = h2f2(gg);  \
        c3 = fmaf(fv.x, c3, iv.x * gv.x);                                   \
        q[((j) & 1) * 2]     = ov.x * tanh_f(c3);                           \
        c3 = fmaf(fv.y, c3, iv.y * gv.y);                                   \
        q[((j) & 1) * 2 + 1] = ov.y * tanh_f(c3);                           \
        if ((j) & 1)                                                        \
            *reinterpret_cast<float4*>(po + ((j) >> 1) * 4) =               \
                make_float4(q[0], q[1], q[2], q[3]);                        \
    }

#define SCAN_P2()                                                           \
    do {                                                                    \
        cin = 0.f;                                                          \
        if (hasprv) {                                                       \
            _Pragma("unroll") for (int s2 = 0; s2 < 7; s2++) {              \
                if (s2 < seg) {                                             \
                    uint32_t psa = smb + PS_B + (uint32_t)(s2 * 64 + hc) * 8; \
                    float P, S;                                             \
                    asm volatile("ld.shared.v2.f32 {%0, %1}, [%2];"         \
                                 : "=f"(P), "=f"(S) : "r"(psa));            \
                    cin = fmaf(P, cin, S);                                  \
                }                                                           \
            }                                                               \
        }                                                                   \
    } while (0)

    // ---- preamble: W (96KB, once per SM) + first row super-A -> buf 0
    {
#pragma unroll
        for (int j = 0; j < 12; j++)
            CPA16(smb + tid * 16 + j * 8192, gw + tid * 16 + j * 8192);
        STAGE_X96(blockIdx.x >> 7, blockIdx.x & 127, 0, 0);
        CPA_COMMIT();
        CPA_WAIT0();
        __syncthreads();
    }

    // B fragment bases (fixed)
    uint32_t bb0[2], bb1[2];
#pragma unroll
    for (int np = 0; np < 2; np++) {
        int oct = ((nw * 32 + np * 16) >> 3) + wo;
        uint32_t sw = (uint32_t)((oct ^ l7) << 4) + (uint32_t)krl * 256;
        bb0[np] = smb + XBUF_B + sw;
        bb1[np] = smb + XBUF_B + 24576 + sw;
    }

#pragma unroll 1
    for (int bh = blockIdx.x; bh < NROWS; bh += GRID) {
        const int b = bh >> 7, h = bh & 127;
        const int nbh = bh + GRID;
        const bool hasprv = (bh != (int)blockIdx.x);
        const int pbh = bh - GRID;
        float* po = out + ((size_t)(((pbh >> 7) & 15) * HCv + hc) * Hv +
                           (pbh & 127)) * Wv + seg * 16;

        uint32_t acc[4][4][2];
#pragma unroll
        for (int mt = 0; mt < 4; mt++)
#pragma unroll
            for (int nt = 0; nt < 4; nt++) {
                acc[mt][nt][0] = 0u;
                acc[mt][nt][1] = 0u;
            }

        // stage super-B of this row into buf 1 (overlaps super-0 MMAs)
        STAGE_X96(b, h, 1, 1);
        CPA_COMMIT();

        float sc = 0.f, sp = 1.f, c3, cin;
        float q[4];

        // ---- super 0 (buf0) + scan pass1 of prev row, interleaved
        KSTEP(0, bb0); SCAN_P1(0);
        KSTEP(1, bb0); SCAN_P1(1);
        KSTEP(2, bb0); SCAN_P1(2); SCAN_P1(3);
        KSTEP(3, bb0); SCAN_P1(4);
        KSTEP(4, bb0); SCAN_P1(5); SCAN_P1(6);
        KSTEP(5, bb0); SCAN_P1(7);

        if (hasprv)
            asm volatile("st.shared.v2.f32 [%0], {%1, %2};"
                         :: "r"(psme), "f"(sp), "f"(sc) : "memory");

        CPA_WAIT0();        // super-B arrived
        __syncthreads();    // buf0 reads done + PS visible

        // prefetch next row's super-A into buf 0
        if (nbh < NROWS) {
            STAGE_X96(nbh >> 7, nbh & 127, 0, 0);
            CPA_COMMIT();
        }

        SCAN_P2();
        c3 = cin;

        // ---- super 1 (buf1) + scan pass3 of prev row, interleaved
        KSTEP(6, bb1);  SCAN_P3(0);
        KSTEP(7, bb1);  SCAN_P3(1); SCAN_P3(2);
        KSTEP(8, bb1);  SCAN_P3(3);
        KSTEP(9, bb1);  SCAN_P3(4); SCAN_P3(5);
        KSTEP(10, bb1); SCAN_P3(6);
        KSTEP(11, bb1); SCAN_P3(7);

        __syncthreads();   // pass3 reads done before gates overwrite

        // ---- epilogue: unpack fp16 acc + bias + activation -> fp16 gates
#pragma unroll
        for (int mt = 0; mt < 4; mt++) {
            const uint32_t glo = smb + GATE_B +
                                 (uint32_t)(mw * 64 + mt * 16 + r) * GROW_B;
            const uint32_t ghi = glo + 8u * GROW_B;
#pragma unroll
            for (int nt = 0; nt < 4; nt++) {
                const uint32_t w2o = (uint32_t)(nw * 16 + nt * 4 + cl) * 4u;
                float2 f01 = h2f2(acc[mt][nt][0]);
                float2 f23 = h2f2(acc[mt][nt][1]);
                float v0 = f01.x + blo[mt];
                float v1 = f01.y + blo[mt];
                float v2 = f23.x + bhi[mt];
                float v3 = f23.y + bhi[mt];
                if (isg) {
                    v0 = tanh_f(v0); v1 = tanh_f(v1);
                    v2 = tanh_f(v2); v3 = tanh_f(v3);
                } else {
                    v0 = sigmoid_f(v0); v1 = sigmoid_f(v1);
                    v2 = sigmoid_f(v2); v3 = sigmoid_f(v3);
                }
                uint32_t p01, p23;
                asm("cvt.rn.f16x2.f32 %0, %1, %2;" : "=r"(p01) : "f"(v1), "f"(v0));
                asm("cvt.rn.f16x2.f32 %0, %1, %2;" : "=r"(p23) : "f"(v3), "f"(v2));
                sts32(glo + w2o, p01);
                sts32(ghi + w2o, p23);
            }
        }

        if (nbh < NROWS) CPA_WAIT0();
        __syncthreads();   // gates visible for next iter's pass1; buf0 ready
    }

    // ---- tail: scan of the last row (non-interleaved)
    {
        const bool hasprv = true;
        const int lbh = (int)blockIdx.x +
                        ((NROWS - 1 - (int)blockIdx.x) / GRID) * GRID;
        float* po = out + ((size_t)(((lbh >> 7) & 15) * HCv + hc) * Hv +
                           (lbh & 127)) * Wv + seg * 16;
        float sc = 0.f, sp = 1.f, c3, cin;
        float q[4];
        SCAN_P1(0); SCAN_P1(1); SCAN_P1(2); SCAN_P1(3);
        SCAN_P1(4); SCAN_P1(5); SCAN_P1(6); SCAN_P1(7);
        asm volatile("st.shared.v2.f32 [%0], {%1, %2};"
                     :: "r"(psme), "f"(sp), "f"(sc) : "memory");
        __syncthreads();
        SCAN_P2();
        c3 = cin;
        SCAN_P3(0); SCAN_P3(1); SCAN_P3(2); SCAN_P3(3);
        SCAN_P3(4); SCAN_P3(5); SCAN_P3(6); SCAN_P3(7);
    }
}

extern "C" void kernel_launch(void* const* d_in, const int* in_sizes, int n_in,
                              void* d_out, int out_size) {
    const float* x    = (const float*)d_in[0];
    const float* wgt  = (const float*)d_in[1];
    const float* bias = (const float*)d_in[2];
    float* out = (float*)d_out;

    cudaFuncSetAttribute(rowlstm_fused,
                         cudaFuncAttributeMaxDynamicSharedMemorySize, SMEM_BYTES);

    prep_xw<<<8192, 256>>>(x, wgt);
    rowlstm_fused<<<GRID, 512, SMEM_BYTES>>>(bias, out);
}